// round 11
// baseline (speedup 1.0000x reference)
#include <cuda_runtime.h>
#include <cuda_bf16.h>
#include <cuda_fp16.h>
#include <cstdint>

// ---------------------------------------------------------------------------
// MultiheadAttention forward. T=S=1024, N=8, E=1024, H=16, D=64.
// q,k,v all projected from `query`. Output = concat(out (T,N,E), avg (N,T,S)).
// Round 10: probs as single fp16 (exact to 2^-11); P.V = P_f16 x (Vh+Vl)_f16,
// 2 segments sharing one P load. Projections/scores unchanged (bf16 3-term).
// ---------------------------------------------------------------------------

namespace {
constexpr int T_DIM   = 1024;
constexpr int N_BATCH = 8;
constexpr int E_DIM   = 1024;
constexpr int H_HEADS = 16;
constexpr int D_HEAD  = 64;
constexpr int B_TOTAL = N_BATCH * H_HEADS;   // 128
constexpr int M_ROWS  = T_DIM * N_BATCH;     // 8192
constexpr int F3      = 3 * E_DIM;           // 3072
}

// Scratch (module-level device globals; no runtime allocation).
__device__ __align__(1024) float g_scores[(size_t)B_TOTAL * T_DIM * T_DIM];     // 537 MB
__device__ __align__(1024) __nv_bfloat16 g_qkv_hi[(size_t)M_ROWS * F3];
__device__ __align__(1024) __nv_bfloat16 g_qkv_lo[(size_t)M_ROWS * F3];
__device__ __align__(1024) __half g_pf16[(size_t)B_TOTAL * T_DIM * T_DIM];      // 268 MB probs
__device__ __align__(1024) __half g_vt_hi[(size_t)B_TOTAL * D_HEAD * T_DIM];    // f16 V^T hi
__device__ __align__(1024) __half g_vt_lo[(size_t)B_TOTAL * D_HEAD * T_DIM];    // f16 V^T lo
__device__ __align__(1024) __nv_bfloat16 g_at_hi[(size_t)M_ROWS * E_DIM];
__device__ __align__(1024) __nv_bfloat16 g_at_lo[(size_t)M_ROWS * E_DIM];
__device__ __align__(1024) __nv_bfloat16 g_qry_hi[(size_t)M_ROWS * E_DIM];
__device__ __align__(1024) __nv_bfloat16 g_qry_lo[(size_t)M_ROWS * E_DIM];
__device__ __align__(1024) __nv_bfloat16 g_w1_hi[(size_t)F3 * E_DIM];
__device__ __align__(1024) __nv_bfloat16 g_w1_lo[(size_t)F3 * E_DIM];
__device__ __align__(1024) __nv_bfloat16 g_w2_hi[(size_t)E_DIM * E_DIM];
__device__ __align__(1024) __nv_bfloat16 g_w2_lo[(size_t)E_DIM * E_DIM];

// ============================ low-level helpers =============================

__device__ __forceinline__ uint32_t smem_to_u32(const void* smem_ptr) {
    uint32_t addr;
    asm("{ .reg .u64 tmp; cvta.to.shared.u64 tmp, %1; cvt.u32.u64 %0, tmp; }"
        : "=r"(addr) : "l"(smem_ptr));
    return addr;
}

#define SWZ128(off) ((off) ^ (((off) >> 3) & 0x70))

__device__ __forceinline__ void cp16(uint32_t smem_dst, const void* gsrc) {
    asm volatile("cp.async.cg.shared.global [%0], [%1], 16;"
                 :: "r"(smem_dst), "l"(gsrc) : "memory");
}
#define CP_COMMIT() asm volatile("cp.async.commit_group;" ::: "memory")
template<int NN> __device__ __forceinline__ void cp_wait() {
    asm volatile("cp.async.wait_group %0;" :: "n"(NN) : "memory");
}

__device__ __forceinline__ void ldmatrix_x4(uint32_t* r, uint32_t addr) {
    asm volatile("ldmatrix.sync.aligned.m8n8.x4.shared.b16 {%0,%1,%2,%3}, [%4];"
                 : "=r"(r[0]), "=r"(r[1]), "=r"(r[2]), "=r"(r[3]) : "r"(addr));
}

__device__ __forceinline__ void mma16816(float* c, const uint32_t* a,
                                         uint32_t b0, uint32_t b1) {
    asm volatile(
        "mma.sync.aligned.m16n8k16.row.col.f32.bf16.bf16.f32 "
        "{%0,%1,%2,%3}, {%4,%5,%6,%7}, {%8,%9}, {%0,%1,%2,%3};"
        : "+f"(c[0]), "+f"(c[1]), "+f"(c[2]), "+f"(c[3])
        : "r"(a[0]), "r"(a[1]), "r"(a[2]), "r"(a[3]), "r"(b0), "r"(b1));
}

__device__ __forceinline__ void mma16816h(float* c, const uint32_t* a,
                                          uint32_t b0, uint32_t b1) {
    asm volatile(
        "mma.sync.aligned.m16n8k16.row.col.f32.f16.f16.f32 "
        "{%0,%1,%2,%3}, {%4,%5,%6,%7}, {%8,%9}, {%0,%1,%2,%3};"
        : "+f"(c[0]), "+f"(c[1]), "+f"(c[2]), "+f"(c[3])
        : "r"(a[0]), "r"(a[1]), "r"(a[2]), "r"(a[3]), "r"(b0), "r"(b1));
}

__device__ __forceinline__ void split2(float v, __nv_bfloat16& h, __nv_bfloat16& l) {
    h = __float2bfloat16(v);
    l = __float2bfloat16(v - __bfloat162float(h));
}

__device__ __forceinline__ void split2h(float v, __half& h, __half& l) {
    h = __float2half_rn(v);
    l = __float2half_rn(v - __half2float(h));
}

// ---------------------------------------------------------------------------
// fp32 -> (hi, lo) bf16 split (inputs: query, weights)
// ---------------------------------------------------------------------------
__global__ void split_kernel(const float4* __restrict__ x,
                             __nv_bfloat162* __restrict__ hi,
                             __nv_bfloat162* __restrict__ lo, int n4)
{
    int i = blockIdx.x * blockDim.x + threadIdx.x;
    if (i >= n4) return;
    float4 v = x[i];
    __nv_bfloat16 hx, hy, hz, hw, lx, ly, lz, lw;
    split2(v.x, hx, lx); split2(v.y, hy, ly);
    split2(v.z, hz, lz); split2(v.w, hw, lw);
    hi[2*i]   = __nv_bfloat162(hx, hy);
    hi[2*i+1] = __nv_bfloat162(hz, hw);
    lo[2*i]   = __nv_bfloat162(lx, ly);
    lo[2*i+1] = __nv_bfloat162(lz, lw);
}

// ---------------------------------------------------------------------------
// mma.sync bf16-split NT GEMM (projections): 3 segments, CTA 128x128, BK=64,
// 3-stage pipeline, one barrier per chunk.
// ---------------------------------------------------------------------------
namespace mg {
constexpr int STAGE    = 32768;
constexpr int SM_TOTAL = 98304;
constexpr int NCHUNK   = 48;
}

__device__ __forceinline__ void mg_load(
    uint32_t sbase, int p,
    const __nv_bfloat16* __restrict__ Aseg, const __nv_bfloat16* __restrict__ Bseg,
    int m0, int n0, int k0, int tid)
{
    uint32_t a_s = sbase + p * mg::STAGE;
    uint32_t b_s = a_s + 16384;
    #pragma unroll
    for (int j = tid; j < 1024; j += 256) {
        int r = j >> 3, c = j & 7;
        uint32_t off = (uint32_t)(r * 128 + c * 16);
        cp16(a_s + SWZ128(off), Aseg + (size_t)(m0 + r) * 1024 + k0 + c * 8);
    }
    #pragma unroll
    for (int j = tid; j < 1024; j += 256) {
        int r = j >> 3, c = j & 7;
        uint32_t off = (uint32_t)(r * 128 + c * 16);
        cp16(b_s + SWZ128(off), Bseg + (size_t)(n0 + r) * 1024 + k0 + c * 8);
    }
    CP_COMMIT();
}

template<bool SPLIT>
__global__ __launch_bounds__(256, 2)
void mg_gemm(const __nv_bfloat16* __restrict__ Ahi, const __nv_bfloat16* __restrict__ Alo,
             const __nv_bfloat16* __restrict__ Bhi, const __nv_bfloat16* __restrict__ Blo,
             float* __restrict__ C, __nv_bfloat16* __restrict__ Chi,
             __nv_bfloat16* __restrict__ Clo, int ldc,
             const float* __restrict__ bias, int qcols)
{
    extern __shared__ char smem[];
    const uint32_t sbase = smem_to_u32(smem);
    const int tid  = threadIdx.x;
    const int wid  = tid >> 5;
    const int lane = tid & 31;
    const int m0   = blockIdx.y * 128;
    const int n0   = blockIdx.x * 128;
    const int wm   = (wid & 3) * 32;
    const int wn   = (wid >> 2) * 64;

    float acc[2][8][4];
    #pragma unroll
    for (int a = 0; a < 2; a++)
        #pragma unroll
        for (int b = 0; b < 8; b++)
            #pragma unroll
            for (int c = 0; c < 4; c++) acc[a][b][c] = 0.f;

    const int lrow  = lane & 15;
    const int lhalf = (lane >> 4) * 16;

    const __nv_bfloat16* Asegs[3] = { Ahi, Alo, Ahi };
    const __nv_bfloat16* Bsegs[3] = { Bhi, Bhi, Blo };

    mg_load(sbase, 0, Asegs[0], Bsegs[0], m0, n0, 0,  tid);
    mg_load(sbase, 1, Asegs[0], Bsegs[0], m0, n0, 64, tid);

    for (int i = 0; i < mg::NCHUNK; i++) {
        const int p = i % 3;
        if (i >= mg::NCHUNK - 1) cp_wait<0>(); else cp_wait<1>();
        __syncthreads();
        const int nx = i + 2;
        if (nx < mg::NCHUNK) {
            const int seg = nx >> 4;
            mg_load(sbase, nx % 3, Asegs[seg], Bsegs[seg], m0, n0, (nx & 15) * 64, tid);
        }

        const uint32_t a_s = sbase + p * mg::STAGE;
        const uint32_t b_s = a_s + 16384;
        #pragma unroll
        for (int k = 0; k < 4; k++) {
            uint32_t af[2][4], bfm[4][4];
            #pragma unroll
            for (int mi = 0; mi < 2; mi++) {
                uint32_t off = (uint32_t)((wm + mi*16 + lrow) * 128 + k*32 + lhalf);
                ldmatrix_x4(af[mi], a_s + SWZ128(off));
            }
            #pragma unroll
            for (int ni = 0; ni < 4; ni++) {
                uint32_t off = (uint32_t)((wn + ni*16 + lrow) * 128 + k*32 + lhalf);
                ldmatrix_x4(bfm[ni], b_s + SWZ128(off));
            }
            #pragma unroll
            for (int mi = 0; mi < 2; mi++)
                #pragma unroll
                for (int ni = 0; ni < 4; ni++) {
                    mma16816(acc[mi][2*ni+0], af[mi], bfm[ni][0], bfm[ni][2]);
                    mma16816(acc[mi][2*ni+1], af[mi], bfm[ni][1], bfm[ni][3]);
                }
        }
    }

    const int r0 = lane >> 2;
    const int cp = (lane & 3) * 2;
    #pragma unroll
    for (int mi = 0; mi < 2; mi++) {
        #pragma unroll
        for (int half = 0; half < 2; half++) {
            const int row = m0 + wm + mi*16 + r0 + half*8;
            #pragma unroll
            for (int nj = 0; nj < 8; nj++) {
                const int col = n0 + wn + nj*8 + cp;
                float v0 = acc[mi][nj][half*2+0];
                float v1 = acc[mi][nj][half*2+1];
                if (bias) { v0 += bias[col]; v1 += bias[col+1]; }
                if (col < qcols) { v0 *= 0.125f; v1 *= 0.125f; }
                const size_t idx = (size_t)row * ldc + col;
                if (SPLIT) {
                    __nv_bfloat16 h0, l0, h1, l1;
                    split2(v0, h0, l0); split2(v1, h1, l1);
                    *reinterpret_cast<__nv_bfloat162*>(Chi + idx) = __nv_bfloat162(h0, h1);
                    *reinterpret_cast<__nv_bfloat162*>(Clo + idx) = __nv_bfloat162(l0, l1);
                } else {
                    *reinterpret_cast<float2*>(C + idx) = make_float2(v0, v1);
                }
            }
        }
    }
}

// ---------------------------------------------------------------------------
// Transpose v (from qkv bf16 splits) -> vt [b][d][s] as f16 hi/lo. 64x64 tiles.
// ---------------------------------------------------------------------------
__global__ void vtrans_kernel(const __nv_bfloat16* __restrict__ qkv_hi,
                              const __nv_bfloat16* __restrict__ qkv_lo,
                              __half* __restrict__ vt_hi,
                              __half* __restrict__ vt_lo)
{
    const int z  = blockIdx.x;
    const int sb = blockIdx.y * 64;
    const int nb = z >> 4, h = z & 15;
    __shared__ __half th[64][66];
    __shared__ __half tl[64][66];
    const int tid = threadIdx.x;
    for (int i = tid; i < 64*32; i += 256) {
        int r = i >> 5, dp = (i & 31) * 2;
        size_t src = (size_t)((sb + r) * 8 + nb) * 3072 + 2048 + h * 64 + dp;
        __nv_bfloat162 vh = *reinterpret_cast<const __nv_bfloat162*>(qkv_hi + src);
        __nv_bfloat162 vl = *reinterpret_cast<const __nv_bfloat162*>(qkv_lo + src);
        float v0 = __bfloat162float(vh.x) + __bfloat162float(vl.x);
        float v1 = __bfloat162float(vh.y) + __bfloat162float(vl.y);
        __half h0, l0, h1, l1;
        split2h(v0, h0, l0); split2h(v1, h1, l1);
        th[r][dp] = h0; th[r][dp+1] = h1;
        tl[r][dp] = l0; tl[r][dp+1] = l1;
    }
    __syncthreads();
    for (int i = tid; i < 64*32; i += 256) {
        int d = i >> 5, sp = (i & 31) * 2;
        size_t dst = (size_t)z * 65536 + (size_t)d * 1024 + sb + sp;
        *reinterpret_cast<__half2*>(vt_hi + dst) = __half2(th[sp][d], th[sp+1][d]);
        *reinterpret_cast<__half2*>(vt_lo + dst) = __half2(tl[sp][d], tl[sp+1][d]);
    }
}

// ---------------------------------------------------------------------------
// Scores GEMM: scores[b][t][s] = q_b[t,:].k_b[s,:]  (3 segments of K=64)
// ---------------------------------------------------------------------------
namespace sc {
constexpr int STAGE    = 32768;
constexpr int SM_TOTAL = 98304;
}

__device__ __forceinline__ void sc_load(
    uint32_t sbase, int stage,
    const __nv_bfloat16* __restrict__ Aseg, const __nv_bfloat16* __restrict__ Bseg,
    int m0, int n0, int tid)
{
    uint32_t a_s = sbase + stage * sc::STAGE;
    uint32_t b_s = a_s + 16384;
    #pragma unroll
    for (int j = tid; j < 1024; j += 256) {
        int r = j >> 3, c = j & 7;
        uint32_t off = (uint32_t)(r * 128 + c * 16);
        cp16(a_s + SWZ128(off), Aseg + (size_t)(m0 + r) * 24576 + c * 8);
    }
    #pragma unroll
    for (int j = tid; j < 1024; j += 256) {
        int r = j >> 3, c = j & 7;
        uint32_t off = (uint32_t)(r * 128 + c * 16);
        cp16(b_s + SWZ128(off), Bseg + (size_t)(n0 + r) * 24576 + c * 8);
    }
    CP_COMMIT();
}

__global__ __launch_bounds__(256, 2)
void sc_gemm(const __nv_bfloat16* __restrict__ qkv_hi,
             const __nv_bfloat16* __restrict__ qkv_lo,
             float* __restrict__ scores)
{
    extern __shared__ char smem[];
    const uint32_t sbase = smem_to_u32(smem);
    const int tid  = threadIdx.x;
    const int wid  = tid >> 5;
    const int lane = tid & 31;
    const int z    = blockIdx.z;
    const size_t qoff = (size_t)(z >> 4) * 3072 + (z & 15) * 64;
    const size_t koff = qoff + 1024;
    const int m0 = blockIdx.y * 128;
    const int n0 = blockIdx.x * 128;

    const __nv_bfloat16* Asegs[3] = { qkv_hi + qoff, qkv_lo + qoff, qkv_hi + qoff };
    const __nv_bfloat16* Bsegs[3] = { qkv_hi + koff, qkv_hi + koff, qkv_lo + koff };

    sc_load(sbase, 0, Asegs[0], Bsegs[0], m0, n0, tid);
    sc_load(sbase, 1, Asegs[1], Bsegs[1], m0, n0, tid);
    sc_load(sbase, 2, Asegs[2], Bsegs[2], m0, n0, tid);

    const int wm = (wid & 3) * 32;
    const int wn = (wid >> 2) * 64;
    const int lrow  = lane & 15;
    const int lhalf = (lane >> 4) * 16;

    float acc[2][8][4];
    #pragma unroll
    for (int a = 0; a < 2; a++)
        #pragma unroll
        for (int b = 0; b < 8; b++)
            #pragma unroll
            for (int c = 0; c < 4; c++) acc[a][b][c] = 0.f;

    #pragma unroll
    for (int s = 0; s < 3; s++) {
        if (s == 0) cp_wait<2>(); else if (s == 1) cp_wait<1>(); else cp_wait<0>();
        __syncthreads();
        const uint32_t a_s = sbase + s * sc::STAGE;
        const uint32_t b_s = a_s + 16384;
        #pragma unroll
        for (int k = 0; k < 4; k++) {
            uint32_t af[2][4], bfm[4][4];
            #pragma unroll
            for (int mi = 0; mi < 2; mi++) {
                uint32_t off = (uint32_t)((wm + mi*16 + lrow) * 128 + k*32 + lhalf);
                ldmatrix_x4(af[mi], a_s + SWZ128(off));
            }
            #pragma unroll
            for (int ni = 0; ni < 4; ni++) {
                uint32_t off = (uint32_t)((wn + ni*16 + lrow) * 128 + k*32 + lhalf);
                ldmatrix_x4(bfm[ni], b_s + SWZ128(off));
            }
            #pragma unroll
            for (int mi = 0; mi < 2; mi++)
                #pragma unroll
                for (int ni = 0; ni < 4; ni++) {
                    mma16816(acc[mi][2*ni+0], af[mi], bfm[ni][0], bfm[ni][2]);
                    mma16816(acc[mi][2*ni+1], af[mi], bfm[ni][1], bfm[ni][3]);
                }
        }
    }

    float* Cb = scores + ((size_t)z << 20);
    const int r0 = lane >> 2;
    const int cp = (lane & 3) * 2;
    #pragma unroll
    for (int mi = 0; mi < 2; mi++) {
        #pragma unroll
        for (int half = 0; half < 2; half++) {
            const int row = m0 + wm + mi*16 + r0 + half*8;
            #pragma unroll
            for (int nj = 0; nj < 8; nj++) {
                const int col = n0 + wn + nj*8 + cp;
                *reinterpret_cast<float2*>(Cb + (size_t)row * 1024 + col) =
                    make_float2(acc[mi][nj][half*2+0], acc[mi][nj][half*2+1]);
            }
        }
    }
}

// ---------------------------------------------------------------------------
// Fused softmax + head-average. One block per (t, n); warp h = head h.
// Softmax in registers; fp32 probs staged in smem; avg computed from fp32.
// Probs written as a single fp16 plane.
// ---------------------------------------------------------------------------
__global__ __launch_bounds__(512, 2)
void softmax_avg_kernel(const float* __restrict__ scores,
                        __half* __restrict__ pf,
                        float* __restrict__ avg)
{
    extern __shared__ float sm[];                 // [16][1024]
    const int t  = blockIdx.x;
    const int n  = blockIdx.y;
    const int h  = threadIdx.x >> 5;
    const int lane = threadIdx.x & 31;
    const size_t b = (size_t)(n * 16 + h);
    const float4* row4 = reinterpret_cast<const float4*>(
        scores + (b << 20) + ((size_t)t << 10));

    float4 v[8];
    #pragma unroll
    for (int j = 0; j < 8; j++) v[j] = row4[j * 32 + lane];

    float m = -1e30f;
    #pragma unroll
    for (int j = 0; j < 8; j++)
        m = fmaxf(m, fmaxf(fmaxf(v[j].x, v[j].y), fmaxf(v[j].z, v[j].w)));
    #pragma unroll
    for (int o = 16; o > 0; o >>= 1) m = fmaxf(m, __shfl_xor_sync(0xffffffffu, m, o));

    float s = 0.f;
    #pragma unroll
    for (int j = 0; j < 8; j++) {
        v[j].x = __expf(v[j].x - m); v[j].y = __expf(v[j].y - m);
        v[j].z = __expf(v[j].z - m); v[j].w = __expf(v[j].w - m);
        s += v[j].x + v[j].y + v[j].z + v[j].w;
    }
    #pragma unroll
    for (int o = 16; o > 0; o >>= 1) s += __shfl_xor_sync(0xffffffffu, s, o);
    const float inv = 1.0f / s;

    __half2* pf2 = reinterpret_cast<__half2*>(pf + (b << 20) + ((size_t)t << 10));
    float* smh = sm + h * 1024;
    #pragma unroll
    for (int j = 0; j < 8; j++) {
        float p0 = v[j].x * inv, p1 = v[j].y * inv;
        float p2 = v[j].z * inv, p3 = v[j].w * inv;
        const int e = (j * 32 + lane) * 4;
        *reinterpret_cast<float4*>(smh + e) = make_float4(p0, p1, p2, p3);
        pf2[e >> 1]       = __half2(__float2half_rn(p0), __float2half_rn(p1));
        pf2[(e >> 1) + 1] = __half2(__float2half_rn(p2), __float2half_rn(p3));
    }

    if (avg) {
        __syncthreads();
        const int c = threadIdx.x * 2;
        float a0 = 0.f, a1 = 0.f;
        #pragma unroll
        for (int r = 0; r < 16; r++) {
            a0 += sm[r * 1024 + c];
            a1 += sm[r * 1024 + c + 1];
        }
        *reinterpret_cast<float2*>(avg + ((size_t)n << 20) + ((size_t)t << 10) + c) =
            make_float2(a0 * 0.0625f, a1 * 0.0625f);
    }
}

// ---------------------------------------------------------------------------
// P.V GEMM (fp16): attn = P_f16 . (Vh + Vl)^T. One P tile per chunk serves
// both V segments (same accumulator). CTA 128x64, 16 chunks, 3-stage pipeline.
// ---------------------------------------------------------------------------
namespace pv {
constexpr int STAGE    = 32768;     // P 16KB + Vh 8KB + Vl 8KB
constexpr int SM_TOTAL = 98304;
constexpr int NCHUNK   = 16;
}

__device__ __forceinline__ void pv_load(
    uint32_t sbase, int p,
    const __half* __restrict__ P, const __half* __restrict__ Vh,
    const __half* __restrict__ Vl, int m0, int k0, int tid)
{
    uint32_t p_s  = sbase + p * pv::STAGE;
    uint32_t vh_s = p_s + 16384;
    uint32_t vl_s = p_s + 24576;
    #pragma unroll
    for (int j = tid; j < 1024; j += 256) {
        int r = j >> 3, c = j & 7;
        uint32_t off = (uint32_t)(r * 128 + c * 16);
        cp16(p_s + SWZ128(off), P + (size_t)(m0 + r) * 1024 + k0 + c * 8);
    }
    #pragma unroll
    for (int j = tid; j < 512; j += 256) {
        int r = j >> 3, c = j & 7;
        uint32_t off = (uint32_t)(r * 128 + c * 16);
        cp16(vh_s + SWZ128(off), Vh + (size_t)r * 1024 + k0 + c * 8);
    }
    #pragma unroll
    for (int j = tid; j < 512; j += 256) {
        int r = j >> 3, c = j & 7;
        uint32_t off = (uint32_t)(r * 128 + c * 16);
        cp16(vl_s + SWZ128(off), Vl + (size_t)r * 1024 + k0 + c * 8);
    }
    CP_COMMIT();
}

__global__ __launch_bounds__(256, 2)
void pv_gemm(const __half* __restrict__ pf,
             const __half* __restrict__ vth, const __half* __restrict__ vtl,
             __nv_bfloat16* __restrict__ at_hi, __nv_bfloat16* __restrict__ at_lo)
{
    extern __shared__ char smem[];
    const uint32_t sbase = smem_to_u32(smem);
    const int tid  = threadIdx.x;
    const int wid  = tid >> 5;
    const int lane = tid & 31;
    const int z    = blockIdx.z;
    const int nb   = z >> 4, h = z & 15;
    const int m0   = blockIdx.y * 128;
    const int wm   = (wid & 3) * 32;
    const int wn   = (wid >> 2) * 32;

    const __half* P  = pf  + ((size_t)z << 20);
    const __half* Vh = vth + (size_t)z * 65536;
    const __half* Vl = vtl + (size_t)z * 65536;

    float acc[2][4][4];
    #pragma unroll
    for (int a = 0; a < 2; a++)
        #pragma unroll
        for (int b = 0; b < 4; b++)
            #pragma unroll
            for (int c = 0; c < 4; c++) acc[a][b][c] = 0.f;

    const int lrow  = lane & 15;
    const int lhalf = (lane >> 4) * 16;

    pv_load(sbase, 0, P, Vh, Vl, m0, 0,  tid);
    pv_load(sbase, 1, P, Vh, Vl, m0, 64, tid);

    for (int i = 0; i < pv::NCHUNK; i++) {
        const int p = i % 3;
        if (i >= pv::NCHUNK - 1) cp_wait<0>(); else cp_wait<1>();
        __syncthreads();
        const int nx = i + 2;
        if (nx < pv::NCHUNK) {
            pv_load(sbase, nx % 3, P, Vh, Vl, m0, nx * 64, tid);
        }

        const uint32_t p_s  = sbase + p * pv::STAGE;
        const uint32_t vh_s = p_s + 16384;
        const uint32_t vl_s = p_s + 24576;
        #pragma unroll
        for (int k = 0; k < 4; k++) {
            uint32_t af[2][4], bh[2][4], bl[2][4];
            #pragma unroll
            for (int mi = 0; mi < 2; mi++) {
                uint32_t off = (uint32_t)((wm + mi*16 + lrow) * 128 + k*32 + lhalf);
                ldmatrix_x4(af[mi], p_s + SWZ128(off));
            }
            #pragma unroll
            for (int ni = 0; ni < 2; ni++) {
                uint32_t off = (uint32_t)((wn + ni*16 + lrow) * 128 + k*32 + lhalf);
                ldmatrix_x4(bh[ni], vh_s + SWZ128(off));
                ldmatrix_x4(bl[ni], vl_s + SWZ128(off));
            }
            #pragma unroll
            for (int mi = 0; mi < 2; mi++)
                #pragma unroll
                for (int ni = 0; ni < 2; ni++) {
                    mma16816h(acc[mi][2*ni+0], af[mi], bh[ni][0], bh[ni][2]);
                    mma16816h(acc[mi][2*ni+1], af[mi], bh[ni][1], bh[ni][3]);
                    mma16816h(acc[mi][2*ni+0], af[mi], bl[ni][0], bl[ni][2]);
                    mma16816h(acc[mi][2*ni+1], af[mi], bl[ni][1], bl[ni][3]);
                }
        }
    }

    const int r0 = lane >> 2;
    const int cp = (lane & 3) * 2;
    #pragma unroll
    for (int mi = 0; mi < 2; mi++) {
        #pragma unroll
        for (int half = 0; half < 2; half++) {
            const int t = m0 + wm + mi*16 + r0 + half*8;
            #pragma unroll
            for (int nj = 0; nj < 4; nj++) {
                const int d = wn + nj*8 + cp;
                float v0 = acc[mi][nj][half*2+0];
                float v1 = acc[mi][nj][half*2+1];
                const size_t idx = (size_t)(t * 8 + nb) * 1024 + h * 64 + d;
                __nv_bfloat16 h0, l0, h1, l1;
                split2(v0, h0, l0); split2(v1, h1, l1);
                *reinterpret_cast<__nv_bfloat162*>(at_hi + idx) = __nv_bfloat162(h0, h1);
                *reinterpret_cast<__nv_bfloat162*>(at_lo + idx) = __nv_bfloat162(l0, l1);
            }
        }
    }
}

// ---------------------------------------------------------------------------
// kernel_launch
// ---------------------------------------------------------------------------
extern "C" void kernel_launch(void* const* d_in, const int* in_sizes, int n_in,
                              void* d_out, int out_size)
{
    const float* query = (const float*)d_in[0];
    const float* ipw   = (const float*)d_in[3];
    const float* ipb   = (const float*)d_in[4];
    const float* opw   = (const float*)d_in[5];
    const float* opb   = (const float*)d_in[6];
    float* out = (float*)d_out;

    void* p;
    cudaGetSymbolAddress(&p, g_scores); float* scores = (float*)p;
    cudaGetSymbolAddress(&p, g_qkv_hi); __nv_bfloat16* qkv_hi = (__nv_bfloat16*)p;
    cudaGetSymbolAddress(&p, g_qkv_lo); __nv_bfloat16* qkv_lo = (__nv_bfloat16*)p;
    cudaGetSymbolAddress(&p, g_pf16);   __half* pf16 = (__half*)p;
    cudaGetSymbolAddress(&p, g_vt_hi);  __half* vt_hi = (__half*)p;
    cudaGetSymbolAddress(&p, g_vt_lo);  __half* vt_lo = (__half*)p;
    cudaGetSymbolAddress(&p, g_at_hi);  __nv_bfloat16* at_hi  = (__nv_bfloat16*)p;
    cudaGetSymbolAddress(&p, g_at_lo);  __nv_bfloat16* at_lo  = (__nv_bfloat16*)p;
    cudaGetSymbolAddress(&p, g_qry_hi); __nv_bfloat16* qry_hi = (__nv_bfloat16*)p;
    cudaGetSymbolAddress(&p, g_qry_lo); __nv_bfloat16* qry_lo = (__nv_bfloat16*)p;
    cudaGetSymbolAddress(&p, g_w1_hi);  __nv_bfloat16* w1_hi  = (__nv_bfloat16*)p;
    cudaGetSymbolAddress(&p, g_w1_lo);  __nv_bfloat16* w1_lo  = (__nv_bfloat16*)p;
    cudaGetSymbolAddress(&p, g_w2_hi);  __nv_bfloat16* w2_hi  = (__nv_bfloat16*)p;
    cudaGetSymbolAddress(&p, g_w2_lo);  __nv_bfloat16* w2_lo  = (__nv_bfloat16*)p;

    cudaFuncSetAttribute(mg_gemm<true>,  cudaFuncAttributeMaxDynamicSharedMemorySize, mg::SM_TOTAL);
    cudaFuncSetAttribute(mg_gemm<false>, cudaFuncAttributeMaxDynamicSharedMemorySize, mg::SM_TOTAL);
    cudaFuncSetAttribute(sc_gemm, cudaFuncAttributeMaxDynamicSharedMemorySize, sc::SM_TOTAL);
    cudaFuncSetAttribute(pv_gemm, cudaFuncAttributeMaxDynamicSharedMemorySize, pv::SM_TOTAL);
    cudaFuncSetAttribute(softmax_avg_kernel, cudaFuncAttributeMaxDynamicSharedMemorySize, 65536);

    // 0) input splits
    split_kernel<<<(M_ROWS*E_DIM/4)/256, 256>>>((const float4*)query,
        (__nv_bfloat162*)qry_hi, (__nv_bfloat162*)qry_lo, M_ROWS*E_DIM/4);
    split_kernel<<<(F3*E_DIM/4)/256, 256>>>((const float4*)ipw,
        (__nv_bfloat162*)w1_hi, (__nv_bfloat162*)w1_lo, F3*E_DIM/4);
    split_kernel<<<(E_DIM*E_DIM/4)/256, 256>>>((const float4*)opw,
        (__nv_bfloat162*)w2_hi, (__nv_bfloat162*)w2_lo, E_DIM*E_DIM/4);

    // 1) QKV projection -> bf16 hi/lo splits (bias + q-scale in epilogue)
    mg_gemm<true><<<dim3(F3/128, M_ROWS/128), 256, mg::SM_TOTAL>>>(
        qry_hi, qry_lo, w1_hi, w1_lo, nullptr, qkv_hi, qkv_lo, F3, ipb, E_DIM);

    // 1b) transpose v part -> f16 V^T splits
    vtrans_kernel<<<dim3(B_TOTAL, T_DIM/64), 256>>>(qkv_hi, qkv_lo, vt_hi, vt_lo);

    // 2) scores (tensor): raw fp32
    sc_gemm<<<dim3(T_DIM/128, T_DIM/128, B_TOTAL), 256, sc::SM_TOTAL>>>(
        qkv_hi, qkv_lo, scores);

    // 3) fused softmax + avg; probs -> single fp16 plane
    float* avg_ptr = ((long long)out_size >= 2LL * M_ROWS * E_DIM)
                     ? out + (size_t)M_ROWS * E_DIM : nullptr;
    softmax_avg_kernel<<<dim3(T_DIM, N_BATCH), 512, 65536>>>(scores, pf16, avg_ptr);

    // 4) P.V (fp16 tensor) -> attn bf16 hi/lo splits
    pv_gemm<<<dim3(1, T_DIM/128, B_TOTAL), 256, pv::SM_TOTAL>>>(
        pf16, vt_hi, vt_lo, at_hi, at_lo);

    // 5) output projection (tensor): out = attn . opw^T + opb
    mg_gemm<false><<<dim3(E_DIM/128, M_ROWS/128), 256, mg::SM_TOTAL>>>(
        at_hi, at_lo, w2_hi, w2_lo, out, nullptr, nullptr, E_DIM, opb, 0);
}

// round 15
// speedup vs baseline: 1.5446x; 1.5446x over previous
#include <cuda_runtime.h>
#include <cuda_bf16.h>
#include <cuda_fp16.h>
#include <cstdint>

// ---------------------------------------------------------------------------
// MultiheadAttention forward. T=S=1024, N=8, E=1024, H=16, D=64.
// q,k,v all projected from `query`. Output = concat(out (T,N,E), avg (N,T,S)).
// Round 12: single-fetch hi/lo staging in split GEMMs (each operand tile
// loaded ONCE per K-chunk; all 3 split terms computed from it). fp16 probs.
// ---------------------------------------------------------------------------

namespace {
constexpr int T_DIM   = 1024;
constexpr int N_BATCH = 8;
constexpr int E_DIM   = 1024;
constexpr int H_HEADS = 16;
constexpr int D_HEAD  = 64;
constexpr int B_TOTAL = N_BATCH * H_HEADS;   // 128
constexpr int M_ROWS  = T_DIM * N_BATCH;     // 8192
constexpr int F3      = 3 * E_DIM;           // 3072
}

// Scratch (module-level device globals; no runtime allocation).
__device__ __align__(1024) float g_scores[(size_t)B_TOTAL * T_DIM * T_DIM];     // 537 MB
__device__ __align__(1024) __nv_bfloat16 g_qkv_hi[(size_t)M_ROWS * F3];
__device__ __align__(1024) __nv_bfloat16 g_qkv_lo[(size_t)M_ROWS * F3];
__device__ __align__(1024) __half g_pf16[(size_t)B_TOTAL * T_DIM * T_DIM];      // 268 MB probs
__device__ __align__(1024) __half g_vt_hi[(size_t)B_TOTAL * D_HEAD * T_DIM];
__device__ __align__(1024) __half g_vt_lo[(size_t)B_TOTAL * D_HEAD * T_DIM];
__device__ __align__(1024) __nv_bfloat16 g_at_hi[(size_t)M_ROWS * E_DIM];
__device__ __align__(1024) __nv_bfloat16 g_at_lo[(size_t)M_ROWS * E_DIM];
__device__ __align__(1024) __nv_bfloat16 g_qry_hi[(size_t)M_ROWS * E_DIM];
__device__ __align__(1024) __nv_bfloat16 g_qry_lo[(size_t)M_ROWS * E_DIM];
__device__ __align__(1024) __nv_bfloat16 g_w1_hi[(size_t)F3 * E_DIM];
__device__ __align__(1024) __nv_bfloat16 g_w1_lo[(size_t)F3 * E_DIM];
__device__ __align__(1024) __nv_bfloat16 g_w2_hi[(size_t)E_DIM * E_DIM];
__device__ __align__(1024) __nv_bfloat16 g_w2_lo[(size_t)E_DIM * E_DIM];

// ============================ low-level helpers =============================

__device__ __forceinline__ uint32_t smem_to_u32(const void* smem_ptr) {
    uint32_t addr;
    asm("{ .reg .u64 tmp; cvta.to.shared.u64 tmp, %1; cvt.u32.u64 %0, tmp; }"
        : "=r"(addr) : "l"(smem_ptr));
    return addr;
}

#define SWZ128(off) ((off) ^ (((off) >> 3) & 0x70))

__device__ __forceinline__ void cp16(uint32_t smem_dst, const void* gsrc) {
    asm volatile("cp.async.cg.shared.global [%0], [%1], 16;"
                 :: "r"(smem_dst), "l"(gsrc) : "memory");
}
#define CP_COMMIT() asm volatile("cp.async.commit_group;" ::: "memory")
template<int NN> __device__ __forceinline__ void cp_wait() {
    asm volatile("cp.async.wait_group %0;" :: "n"(NN) : "memory");
}

__device__ __forceinline__ void ldmatrix_x4(uint32_t* r, uint32_t addr) {
    asm volatile("ldmatrix.sync.aligned.m8n8.x4.shared.b16 {%0,%1,%2,%3}, [%4];"
                 : "=r"(r[0]), "=r"(r[1]), "=r"(r[2]), "=r"(r[3]) : "r"(addr));
}

__device__ __forceinline__ void mma16816(float* c, const uint32_t* a,
                                         uint32_t b0, uint32_t b1) {
    asm volatile(
        "mma.sync.aligned.m16n8k16.row.col.f32.bf16.bf16.f32 "
        "{%0,%1,%2,%3}, {%4,%5,%6,%7}, {%8,%9}, {%0,%1,%2,%3};"
        : "+f"(c[0]), "+f"(c[1]), "+f"(c[2]), "+f"(c[3])
        : "r"(a[0]), "r"(a[1]), "r"(a[2]), "r"(a[3]), "r"(b0), "r"(b1));
}

__device__ __forceinline__ void mma16816h(float* c, const uint32_t* a,
                                          uint32_t b0, uint32_t b1) {
    asm volatile(
        "mma.sync.aligned.m16n8k16.row.col.f32.f16.f16.f32 "
        "{%0,%1,%2,%3}, {%4,%5,%6,%7}, {%8,%9}, {%0,%1,%2,%3};"
        : "+f"(c[0]), "+f"(c[1]), "+f"(c[2]), "+f"(c[3])
        : "r"(a[0]), "r"(a[1]), "r"(a[2]), "r"(a[3]), "r"(b0), "r"(b1));
}

__device__ __forceinline__ void split2(float v, __nv_bfloat16& h, __nv_bfloat16& l) {
    h = __float2bfloat16(v);
    l = __float2bfloat16(v - __bfloat162float(h));
}

__device__ __forceinline__ void split2h(float v, __half& h, __half& l) {
    h = __float2half_rn(v);
    l = __float2half_rn(v - __half2float(h));
}

// ---------------------------------------------------------------------------
// fp32 -> (hi, lo) bf16 split (inputs: query, weights)
// ---------------------------------------------------------------------------
__global__ void split_kernel(const float4* __restrict__ x,
                             __nv_bfloat162* __restrict__ hi,
                             __nv_bfloat162* __restrict__ lo, int n4)
{
    int i = blockIdx.x * blockDim.x + threadIdx.x;
    if (i >= n4) return;
    float4 v = x[i];
    __nv_bfloat16 hx, hy, hz, hw, lx, ly, lz, lw;
    split2(v.x, hx, lx); split2(v.y, hy, ly);
    split2(v.z, hz, lz); split2(v.w, hw, lw);
    hi[2*i]   = __nv_bfloat162(hx, hy);
    hi[2*i+1] = __nv_bfloat162(hz, hw);
    lo[2*i]   = __nv_bfloat162(lx, ly);
    lo[2*i+1] = __nv_bfloat162(lz, lw);
}

// ---------------------------------------------------------------------------
// mma.sync bf16-split NT GEMM (projections): C = A.B^T with 3-term split
// (Ah.Bh + Al.Bh + Ah.Bl). CTA 128x128. BK=32; each stage packs hi|lo in one
// 128B row: A-plane 16KB [r*128 + half*64 + col], B-plane 16KB. Every operand
// tile fetched ONCE per K-chunk; all three terms computed from the same stage.
// 3-stage pipeline, one barrier per chunk.
// ---------------------------------------------------------------------------
namespace mg {
constexpr int STAGE    = 32768;   // A-plane 16KB + B-plane 16KB
constexpr int SM_TOTAL = 98304;   // 3 stages
constexpr int NCHUNK   = 32;      // K=1024 / BK=32
}

__device__ __forceinline__ void mg_load(
    uint32_t sbase, int p,
    const __nv_bfloat16* __restrict__ Ahi, const __nv_bfloat16* __restrict__ Alo,
    const __nv_bfloat16* __restrict__ Bhi, const __nv_bfloat16* __restrict__ Blo,
    int m0, int n0, int k0, int tid)
{
    uint32_t a_s = sbase + p * mg::STAGE;
    uint32_t b_s = a_s + 16384;
    #pragma unroll
    for (int j = tid; j < 1024; j += 256) {        // A-plane: 128 rows x (hi 64B | lo 64B)
        int r = j >> 3, c = j & 7;
        int half = c >> 2, cc = c & 3;
        uint32_t off = (uint32_t)(r * 128 + half * 64 + cc * 16);
        const __nv_bfloat16* src = (half ? Alo : Ahi) + (size_t)(m0 + r) * 1024 + k0 + cc * 8;
        cp16(a_s + SWZ128(off), src);
    }
    #pragma unroll
    for (int j = tid; j < 1024; j += 256) {        // B-plane
        int r = j >> 3, c = j & 7;
        int half = c >> 2, cc = c & 3;
        uint32_t off = (uint32_t)(r * 128 + half * 64 + cc * 16);
        const __nv_bfloat16* src = (half ? Blo : Bhi) + (size_t)(n0 + r) * 1024 + k0 + cc * 8;
        cp16(b_s + SWZ128(off), src);
    }
    CP_COMMIT();
}

template<bool SPLIT>
__global__ __launch_bounds__(256, 2)
void mg_gemm(const __nv_bfloat16* __restrict__ Ahi, const __nv_bfloat16* __restrict__ Alo,
             const __nv_bfloat16* __restrict__ Bhi, const __nv_bfloat16* __restrict__ Blo,
             float* __restrict__ C, __nv_bfloat16* __restrict__ Chi,
             __nv_bfloat16* __restrict__ Clo, int ldc,
             const float* __restrict__ bias, int qcols)
{
    extern __shared__ char smem[];
    const uint32_t sbase = smem_to_u32(smem);
    const int tid  = threadIdx.x;
    const int wid  = tid >> 5;
    const int lane = tid & 31;
    const int m0   = blockIdx.y * 128;
    const int n0   = blockIdx.x * 128;
    const int wm   = (wid & 3) * 32;
    const int wn   = (wid >> 2) * 64;

    float acc[2][8][4];
    #pragma unroll
    for (int a = 0; a < 2; a++)
        #pragma unroll
        for (int b = 0; b < 8; b++)
            #pragma unroll
            for (int c = 0; c < 4; c++) acc[a][b][c] = 0.f;

    const int lrow  = lane & 15;
    const int lhalf = (lane >> 4) * 16;

    mg_load(sbase, 0, Ahi, Alo, Bhi, Blo, m0, n0, 0,  tid);
    mg_load(sbase, 1, Ahi, Alo, Bhi, Blo, m0, n0, 32, tid);

    for (int i = 0; i < mg::NCHUNK; i++) {
        const int p = i % 3;
        if (i >= mg::NCHUNK - 1) cp_wait<0>(); else cp_wait<1>();
        __syncthreads();
        const int nx = i + 2;
        if (nx < mg::NCHUNK)
            mg_load(sbase, nx % 3, Ahi, Alo, Bhi, Blo, m0, n0, nx * 32, tid);

        const uint32_t a_s = sbase + p * mg::STAGE;
        const uint32_t b_s = a_s + 16384;
        #pragma unroll
        for (int k = 0; k < 2; k++) {              // 2 x k16 within BK=32
            uint32_t ah[2][4], al[2][4], bb[4][4];
            #pragma unroll
            for (int mi = 0; mi < 2; mi++) {
                uint32_t off = (uint32_t)((wm + mi*16 + lrow) * 128 + k*32 + lhalf);
                ldmatrix_x4(ah[mi], a_s + SWZ128(off));
                ldmatrix_x4(al[mi], a_s + SWZ128(off + 64));
            }
            #pragma unroll
            for (int ni = 0; ni < 4; ni++) {       // B hi half
                uint32_t off = (uint32_t)((wn + ni*16 + lrow) * 128 + k*32 + lhalf);
                ldmatrix_x4(bb[ni], b_s + SWZ128(off));
            }
            #pragma unroll
            for (int mi = 0; mi < 2; mi++)
                #pragma unroll
                for (int ni = 0; ni < 4; ni++) {
                    mma16816(acc[mi][2*ni+0], ah[mi], bb[ni][0], bb[ni][2]);
                    mma16816(acc[mi][2*ni+1], ah[mi], bb[ni][1], bb[ni][3]);
                    mma16816(acc[mi][2*ni+0], al[mi], bb[ni][0], bb[ni][2]);
                    mma16816(acc[mi][2*ni+1], al[mi], bb[ni][1], bb[ni][3]);
                }
            #pragma unroll
            for (int ni = 0; ni < 4; ni++) {       // B lo half (reuse bb regs)
                uint32_t off = (uint32_t)((wn + ni*16 + lrow) * 128 + k*32 + lhalf + 64);
                ldmatrix_x4(bb[ni], b_s + SWZ128(off));
            }
            #pragma unroll
            for (int mi = 0; mi < 2; mi++)
                #pragma unroll
                for (int ni = 0; ni < 4; ni++) {
                    mma16816(acc[mi][2*ni+0], ah[mi], bb[ni][0], bb[ni][2]);
                    mma16816(acc[mi][2*ni+1], ah[mi], bb[ni][1], bb[ni][3]);
                }
        }
    }

    const int r0 = lane >> 2;
    const int cp = (lane & 3) * 2;
    #pragma unroll
    for (int mi = 0; mi < 2; mi++) {
        #pragma unroll
        for (int half = 0; half < 2; half++) {
            const int row = m0 + wm + mi*16 + r0 + half*8;
            #pragma unroll
            for (int nj = 0; nj < 8; nj++) {
                const int col = n0 + wn + nj*8 + cp;
                float v0 = acc[mi][nj][half*2+0];
                float v1 = acc[mi][nj][half*2+1];
                if (bias) { v0 += bias[col]; v1 += bias[col+1]; }
                if (col < qcols) { v0 *= 0.125f; v1 *= 0.125f; }
                const size_t idx = (size_t)row * ldc + col;
                if (SPLIT) {
                    __nv_bfloat16 h0, l0, h1, l1;
                    split2(v0, h0, l0); split2(v1, h1, l1);
                    *reinterpret_cast<__nv_bfloat162*>(Chi + idx) = __nv_bfloat162(h0, h1);
                    *reinterpret_cast<__nv_bfloat162*>(Clo + idx) = __nv_bfloat162(l0, l1);
                } else {
                    *reinterpret_cast<float2*>(C + idx) = make_float2(v0, v1);
                }
            }
        }
    }
}

// ---------------------------------------------------------------------------
// Transpose v (from qkv bf16 splits) -> vt [b][d][s] as f16 hi/lo. 64x64 tiles.
// ---------------------------------------------------------------------------
__global__ void vtrans_kernel(const __nv_bfloat16* __restrict__ qkv_hi,
                              const __nv_bfloat16* __restrict__ qkv_lo,
                              __half* __restrict__ vt_hi,
                              __half* __restrict__ vt_lo)
{
    const int z  = blockIdx.x;
    const int sb = blockIdx.y * 64;
    const int nb = z >> 4, h = z & 15;
    __shared__ __half th[64][66];
    __shared__ __half tl[64][66];
    const int tid = threadIdx.x;
    for (int i = tid; i < 64*32; i += 256) {
        int r = i >> 5, dp = (i & 31) * 2;
        size_t src = (size_t)((sb + r) * 8 + nb) * 3072 + 2048 + h * 64 + dp;
        __nv_bfloat162 vh = *reinterpret_cast<const __nv_bfloat162*>(qkv_hi + src);
        __nv_bfloat162 vl = *reinterpret_cast<const __nv_bfloat162*>(qkv_lo + src);
        float v0 = __bfloat162float(vh.x) + __bfloat162float(vl.x);
        float v1 = __bfloat162float(vh.y) + __bfloat162float(vl.y);
        __half h0, l0, h1, l1;
        split2h(v0, h0, l0); split2h(v1, h1, l1);
        th[r][dp] = h0; th[r][dp+1] = h1;
        tl[r][dp] = l0; tl[r][dp+1] = l1;
    }
    __syncthreads();
    for (int i = tid; i < 64*32; i += 256) {
        int d = i >> 5, sp = (i & 31) * 2;
        size_t dst = (size_t)z * 65536 + (size_t)d * 1024 + sb + sp;
        *reinterpret_cast<__half2*>(vt_hi + dst) = __half2(th[sp][d], th[sp+1][d]);
        *reinterpret_cast<__half2*>(vt_lo + dst) = __half2(tl[sp][d], tl[sp+1][d]);
    }
}

// ---------------------------------------------------------------------------
// Scores GEMM: scores[b][t][s] = q_b[t,:].k_b[s,:].  K=64. Single-shot
// staging of 4 planes (qh, ql, kh, kl; 16KB each), 3-term split from them.
// ---------------------------------------------------------------------------
namespace sc {
constexpr int SM_TOTAL = 65536;
}

__global__ __launch_bounds__(256, 2)
void sc_gemm(const __nv_bfloat16* __restrict__ qkv_hi,
             const __nv_bfloat16* __restrict__ qkv_lo,
             float* __restrict__ scores)
{
    extern __shared__ char smem[];
    const uint32_t sbase = smem_to_u32(smem);
    const int tid  = threadIdx.x;
    const int wid  = tid >> 5;
    const int lane = tid & 31;
    const int z    = blockIdx.z;
    const size_t qoff = (size_t)(z >> 4) * 3072 + (z & 15) * 64;
    const size_t koff = qoff + 1024;
    const int m0 = blockIdx.y * 128;
    const int n0 = blockIdx.x * 128;

    // 4 planes: 0=qh (rows m0+), 1=ql, 2=kh (rows n0+), 3=kl
    const __nv_bfloat16* bases[4] = { qkv_hi + qoff, qkv_lo + qoff,
                                      qkv_hi + koff, qkv_lo + koff };
    #pragma unroll
    for (int j = tid; j < 4096; j += 256) {
        int plane = j >> 10;
        int jj = j & 1023;
        int r = jj >> 3, c = jj & 7;
        int row0 = (plane < 2) ? m0 : n0;
        uint32_t off = (uint32_t)(plane * 16384 + SWZ128((uint32_t)(r * 128 + c * 16)));
        cp16(sbase + off, bases[plane] + (size_t)(row0 + r) * 24576 + c * 8);
    }
    CP_COMMIT();

    const int wm = (wid & 3) * 32;
    const int wn = (wid >> 2) * 64;
    const int lrow  = lane & 15;
    const int lhalf = (lane >> 4) * 16;

    float acc[2][8][4];
    #pragma unroll
    for (int a = 0; a < 2; a++)
        #pragma unroll
        for (int b = 0; b < 8; b++)
            #pragma unroll
            for (int c = 0; c < 4; c++) acc[a][b][c] = 0.f;

    cp_wait<0>();
    __syncthreads();

    const uint32_t qh_s = sbase;
    const uint32_t ql_s = sbase + 16384;
    const uint32_t kh_s = sbase + 32768;
    const uint32_t kl_s = sbase + 49152;

    #pragma unroll
    for (int k = 0; k < 4; k++) {
        uint32_t ah[2][4], al[2][4], bb[4][4];
        #pragma unroll
        for (int mi = 0; mi < 2; mi++) {
            uint32_t off = (uint32_t)((wm + mi*16 + lrow) * 128 + k*32 + lhalf);
            ldmatrix_x4(ah[mi], qh_s + SWZ128(off));
            ldmatrix_x4(al[mi], ql_s + SWZ128(off));
        }
        #pragma unroll
        for (int ni = 0; ni < 4; ni++) {
            uint32_t off = (uint32_t)((wn + ni*16 + lrow) * 128 + k*32 + lhalf);
            ldmatrix_x4(bb[ni], kh_s + SWZ128(off));
        }
        #pragma unroll
        for (int mi = 0; mi < 2; mi++)
            #pragma unroll
            for (int ni = 0; ni < 4; ni++) {
                mma16816(acc[mi][2*ni+0], ah[mi], bb[ni][0], bb[ni][2]);
                mma16816(acc[mi][2*ni+1], ah[mi], bb[ni][1], bb[ni][3]);
                mma16816(acc[mi][2*ni+0], al[mi], bb[ni][0], bb[ni][2]);
                mma16816(acc[mi][2*ni+1], al[mi], bb[ni][1], bb[ni][3]);
            }
        #pragma unroll
        for (int ni = 0; ni < 4; ni++) {
            uint32_t off = (uint32_t)((wn + ni*16 + lrow) * 128 + k*32 + lhalf);
            ldmatrix_x4(bb[ni], kl_s + SWZ128(off));
        }
        #pragma unroll
        for (int mi = 0; mi < 2; mi++)
            #pragma unroll
            for (int ni = 0; ni < 4; ni++) {
                mma16816(acc[mi][2*ni+0], ah[mi], bb[ni][0], bb[ni][2]);
                mma16816(acc[mi][2*ni+1], ah[mi], bb[ni][1], bb[ni][3]);
            }
    }

    float* Cb = scores + ((size_t)z << 20);
    const int r0 = lane >> 2;
    const int cp = (lane & 3) * 2;
    #pragma unroll
    for (int mi = 0; mi < 2; mi++) {
        #pragma unroll
        for (int half = 0; half < 2; half++) {
            const int row = m0 + wm + mi*16 + r0 + half*8;
            #pragma unroll
            for (int nj = 0; nj < 8; nj++) {
                const int col = n0 + wn + nj*8 + cp;
                *reinterpret_cast<float2*>(Cb + (size_t)row * 1024 + col) =
                    make_float2(acc[mi][nj][half*2+0], acc[mi][nj][half*2+1]);
            }
        }
    }
}

// ---------------------------------------------------------------------------
// Fused softmax + head-average. One block per (t, n); warp h = head h.
// Softmax in registers; fp32 probs staged in smem; avg computed from fp32.
// Probs written as a single fp16 plane (exact to 2^-11 on [0,1]).
// ---------------------------------------------------------------------------
__global__ __launch_bounds__(512, 2)
void softmax_avg_kernel(const float* __restrict__ scores,
                        __half* __restrict__ pf,
                        float* __restrict__ avg)
{
    extern __shared__ float sm[];                 // [16][1024]
    const int t  = blockIdx.x;
    const int n  = blockIdx.y;
    const int h  = threadIdx.x >> 5;
    const int lane = threadIdx.x & 31;
    const size_t b = (size_t)(n * 16 + h);
    const float4* row4 = reinterpret_cast<const float4*>(
        scores + (b << 20) + ((size_t)t << 10));

    float4 v[8];
    #pragma unroll
    for (int j = 0; j < 8; j++) v[j] = row4[j * 32 + lane];

    float m = -1e30f;
    #pragma unroll
    for (int j = 0; j < 8; j++)
        m = fmaxf(m, fmaxf(fmaxf(v[j].x, v[j].y), fmaxf(v[j].z, v[j].w)));
    #pragma unroll
    for (int o = 16; o > 0; o >>= 1) m = fmaxf(m, __shfl_xor_sync(0xffffffffu, m, o));

    float s = 0.f;
    #pragma unroll
    for (int j = 0; j < 8; j++) {
        v[j].x = __expf(v[j].x - m); v[j].y = __expf(v[j].y - m);
        v[j].z = __expf(v[j].z - m); v[j].w = __expf(v[j].w - m);
        s += v[j].x + v[j].y + v[j].z + v[j].w;
    }
    #pragma unroll
    for (int o = 16; o > 0; o >>= 1) s += __shfl_xor_sync(0xffffffffu, s, o);
    const float inv = 1.0f / s;

    __half2* pf2 = reinterpret_cast<__half2*>(pf + (b << 20) + ((size_t)t << 10));
    float* smh = sm + h * 1024;
    #pragma unroll
    for (int j = 0; j < 8; j++) {
        float p0 = v[j].x * inv, p1 = v[j].y * inv;
        float p2 = v[j].z * inv, p3 = v[j].w * inv;
        const int e = (j * 32 + lane) * 4;
        *reinterpret_cast<float4*>(smh + e) = make_float4(p0, p1, p2, p3);
        pf2[e >> 1]       = __half2(__float2half_rn(p0), __float2half_rn(p1));
        pf2[(e >> 1) + 1] = __half2(__float2half_rn(p2), __float2half_rn(p3));
    }

    if (avg) {
        __syncthreads();
        const int c = threadIdx.x * 2;
        float a0 = 0.f, a1 = 0.f;
        #pragma unroll
        for (int r = 0; r < 16; r++) {
            a0 += sm[r * 1024 + c];
            a1 += sm[r * 1024 + c + 1];
        }
        *reinterpret_cast<float2*>(avg + ((size_t)n << 20) + ((size_t)t << 10) + c) =
            make_float2(a0 * 0.0625f, a1 * 0.0625f);
    }
}

// ---------------------------------------------------------------------------
// P.V GEMM (fp16): attn = P_f16 . (Vh + Vl)^T. One P tile per chunk serves
// both V halves (same accumulator). CTA 128x64, 16 chunks, 3-stage pipeline.
// ---------------------------------------------------------------------------
namespace pv {
constexpr int STAGE    = 32768;     // P 16KB + Vh 8KB + Vl 8KB
constexpr int SM_TOTAL = 98304;
constexpr int NCHUNK   = 16;
}

__device__ __forceinline__ void pv_load(
    uint32_t sbase, int p,
    const __half* __restrict__ P, const __half* __restrict__ Vh,
    const __half* __restrict__ Vl, int m0, int k0, int tid)
{
    uint32_t p_s  = sbase + p * pv::STAGE;
    uint32_t vh_s = p_s + 16384;
    uint32_t vl_s = p_s + 24576;
    #pragma unroll
    for (int j = tid; j < 1024; j += 256) {
        int r = j >> 3, c = j & 7;
        uint32_t off = (uint32_t)(r * 128 + c * 16);
        cp16(p_s + SWZ128(off), P + (size_t)(m0 + r) * 1024 + k0 + c * 8);
    }
    #pragma unroll
    for (int j = tid; j < 512; j += 256) {
        int r = j >> 3, c = j & 7;
        uint32_t off = (uint32_t)(r * 128 + c * 16);
        cp16(vh_s + SWZ128(off), Vh + (size_t)r * 1024 + k0 + c * 8);
    }
    #pragma unroll
    for (int j = tid; j < 512; j += 256) {
        int r = j >> 3, c = j & 7;
        uint32_t off = (uint32_t)(r * 128 + c * 16);
        cp16(vl_s + SWZ128(off), Vl + (size_t)r * 1024 + k0 + c * 8);
    }
    CP_COMMIT();
}

__global__ __launch_bounds__(256, 2)
void pv_gemm(const __half* __restrict__ pf,
             const __half* __restrict__ vth, const __half* __restrict__ vtl,
             __nv_bfloat16* __restrict__ at_hi, __nv_bfloat16* __restrict__ at_lo)
{
    extern __shared__ char smem[];
    const uint32_t sbase = smem_to_u32(smem);
    const int tid  = threadIdx.x;
    const int wid  = tid >> 5;
    const int lane = tid & 31;
    const int z    = blockIdx.z;
    const int nb   = z >> 4, h = z & 15;
    const int m0   = blockIdx.y * 128;
    const int wm   = (wid & 3) * 32;
    const int wn   = (wid >> 2) * 32;

    const __half* P  = pf  + ((size_t)z << 20);
    const __half* Vh = vth + (size_t)z * 65536;
    const __half* Vl = vtl + (size_t)z * 65536;

    float acc[2][4][4];
    #pragma unroll
    for (int a = 0; a < 2; a++)
        #pragma unroll
        for (int b = 0; b < 4; b++)
            #pragma unroll
            for (int c = 0; c < 4; c++) acc[a][b][c] = 0.f;

    const int lrow  = lane & 15;
    const int lhalf = (lane >> 4) * 16;

    pv_load(sbase, 0, P, Vh, Vl, m0, 0,  tid);
    pv_load(sbase, 1, P, Vh, Vl, m0, 64, tid);

    for (int i = 0; i < pv::NCHUNK; i++) {
        const int p = i % 3;
        if (i >= pv::NCHUNK - 1) cp_wait<0>(); else cp_wait<1>();
        __syncthreads();
        const int nx = i + 2;
        if (nx < pv::NCHUNK) {
            pv_load(sbase, nx % 3, P, Vh, Vl, m0, nx * 64, tid);
        }

        const uint32_t p_s  = sbase + p * pv::STAGE;
        const uint32_t vh_s = p_s + 16384;
        const uint32_t vl_s = p_s + 24576;
        #pragma unroll
        for (int k = 0; k < 4; k++) {
            uint32_t af[2][4], bh[2][4], bl[2][4];
            #pragma unroll
            for (int mi = 0; mi < 2; mi++) {
                uint32_t off = (uint32_t)((wm + mi*16 + lrow) * 128 + k*32 + lhalf);
                ldmatrix_x4(af[mi], p_s + SWZ128(off));
            }
            #pragma unroll
            for (int ni = 0; ni < 2; ni++) {
                uint32_t off = (uint32_t)((wn + ni*16 + lrow) * 128 + k*32 + lhalf);
                ldmatrix_x4(bh[ni], vh_s + SWZ128(off));
                ldmatrix_x4(bl[ni], vl_s + SWZ128(off));
            }
            #pragma unroll
            for (int mi = 0; mi < 2; mi++)
                #pragma unroll
                for (int ni = 0; ni < 2; ni++) {
                    mma16816h(acc[mi][2*ni+0], af[mi], bh[ni][0], bh[ni][2]);
                    mma16816h(acc[mi][2*ni+1], af[mi], bh[ni][1], bh[ni][3]);
                    mma16816h(acc[mi][2*ni+0], af[mi], bl[ni][0], bl[ni][2]);
                    mma16816h(acc[mi][2*ni+1], af[mi], bl[ni][1], bl[ni][3]);
                }
        }
    }

    const int r0 = lane >> 2;
    const int cp = (lane & 3) * 2;
    #pragma unroll
    for (int mi = 0; mi < 2; mi++) {
        #pragma unroll
        for (int half = 0; half < 2; half++) {
            const int t = m0 + wm + mi*16 + r0 + half*8;
            #pragma unroll
            for (int nj = 0; nj < 4; nj++) {
                const int d = wn + nj*8 + cp;
                float v0 = acc[mi][nj][half*2+0];
                float v1 = acc[mi][nj][half*2+1];
                const size_t idx = (size_t)(t * 8 + nb) * 1024 + h * 64 + d;
                __nv_bfloat16 h0, l0, h1, l1;
                split2(v0, h0, l0); split2(v1, h1, l1);
                *reinterpret_cast<__nv_bfloat162*>(at_hi + idx) = __nv_bfloat162(h0, h1);
                *reinterpret_cast<__nv_bfloat162*>(at_lo + idx) = __nv_bfloat162(l0, l1);
            }
        }
    }
}

// ---------------------------------------------------------------------------
// kernel_launch
// ---------------------------------------------------------------------------
extern "C" void kernel_launch(void* const* d_in, const int* in_sizes, int n_in,
                              void* d_out, int out_size)
{
    const float* query = (const float*)d_in[0];
    const float* ipw   = (const float*)d_in[3];
    const float* ipb   = (const float*)d_in[4];
    const float* opw   = (const float*)d_in[5];
    const float* opb   = (const float*)d_in[6];
    float* out = (float*)d_out;

    void* p;
    cudaGetSymbolAddress(&p, g_scores); float* scores = (float*)p;
    cudaGetSymbolAddress(&p, g_qkv_hi); __nv_bfloat16* qkv_hi = (__nv_bfloat16*)p;
    cudaGetSymbolAddress(&p, g_qkv_lo); __nv_bfloat16* qkv_lo = (__nv_bfloat16*)p;
    cudaGetSymbolAddress(&p, g_pf16);   __half* pf16 = (__half*)p;
    cudaGetSymbolAddress(&p, g_vt_hi);  __half* vt_hi = (__half*)p;
    cudaGetSymbolAddress(&p, g_vt_lo);  __half* vt_lo = (__half*)p;
    cudaGetSymbolAddress(&p, g_at_hi);  __nv_bfloat16* at_hi  = (__nv_bfloat16*)p;
    cudaGetSymbolAddress(&p, g_at_lo);  __nv_bfloat16* at_lo  = (__nv_bfloat16*)p;
    cudaGetSymbolAddress(&p, g_qry_hi); __nv_bfloat16* qry_hi = (__nv_bfloat16*)p;
    cudaGetSymbolAddress(&p, g_qry_lo); __nv_bfloat16* qry_lo = (__nv_bfloat16*)p;
    cudaGetSymbolAddress(&p, g_w1_hi);  __nv_bfloat16* w1_hi  = (__nv_bfloat16*)p;
    cudaGetSymbolAddress(&p, g_w1_lo);  __nv_bfloat16* w1_lo  = (__nv_bfloat16*)p;
    cudaGetSymbolAddress(&p, g_w2_hi);  __nv_bfloat16* w2_hi  = (__nv_bfloat16*)p;
    cudaGetSymbolAddress(&p, g_w2_lo);  __nv_bfloat16* w2_lo  = (__nv_bfloat16*)p;

    cudaFuncSetAttribute(mg_gemm<true>,  cudaFuncAttributeMaxDynamicSharedMemorySize, mg::SM_TOTAL);
    cudaFuncSetAttribute(mg_gemm<false>, cudaFuncAttributeMaxDynamicSharedMemorySize, mg::SM_TOTAL);
    cudaFuncSetAttribute(sc_gemm, cudaFuncAttributeMaxDynamicSharedMemorySize, sc::SM_TOTAL);
    cudaFuncSetAttribute(pv_gemm, cudaFuncAttributeMaxDynamicSharedMemorySize, pv::SM_TOTAL);
    cudaFuncSetAttribute(softmax_avg_kernel, cudaFuncAttributeMaxDynamicSharedMemorySize, 65536);

    // 0) input splits
    split_kernel<<<(M_ROWS*E_DIM/4)/256, 256>>>((const float4*)query,
        (__nv_bfloat162*)qry_hi, (__nv_bfloat162*)qry_lo, M_ROWS*E_DIM/4);
    split_kernel<<<(F3*E_DIM/4)/256, 256>>>((const float4*)ipw,
        (__nv_bfloat162*)w1_hi, (__nv_bfloat162*)w1_lo, F3*E_DIM/4);
    split_kernel<<<(E_DIM*E_DIM/4)/256, 256>>>((const float4*)opw,
        (__nv_bfloat162*)w2_hi, (__nv_bfloat162*)w2_lo, E_DIM*E_DIM/4);

    // 1) QKV projection -> bf16 hi/lo splits (bias + q-scale in epilogue)
    mg_gemm<true><<<dim3(F3/128, M_ROWS/128), 256, mg::SM_TOTAL>>>(
        qry_hi, qry_lo, w1_hi, w1_lo, nullptr, qkv_hi, qkv_lo, F3, ipb, E_DIM);

    // 1b) transpose v part -> f16 V^T splits
    vtrans_kernel<<<dim3(B_TOTAL, T_DIM/64), 256>>>(qkv_hi, qkv_lo, vt_hi, vt_lo);

    // 2) scores (tensor): raw fp32
    sc_gemm<<<dim3(T_DIM/128, T_DIM/128, B_TOTAL), 256, sc::SM_TOTAL>>>(
        qkv_hi, qkv_lo, scores);

    // 3) fused softmax + avg; probs -> single fp16 plane
    float* avg_ptr = ((long long)out_size >= 2LL * M_ROWS * E_DIM)
                     ? out + (size_t)M_ROWS * E_DIM : nullptr;
    softmax_avg_kernel<<<dim3(T_DIM, N_BATCH), 512, 65536>>>(scores, pf16, avg_ptr);

    // 4) P.V (fp16 tensor) -> attn bf16 hi/lo splits
    pv_gemm<<<dim3(1, T_DIM/128, B_TOTAL), 256, pv::SM_TOTAL>>>(
        pf16, vt_hi, vt_lo, at_hi, at_lo);

    // 5) output projection (tensor): out = attn . opw^T + opb
    mg_gemm<false><<<dim3(E_DIM/128, M_ROWS/128), 256, mg::SM_TOTAL>>>(
        at_hi, at_lo, w2_hi, w2_lo, out, nullptr, nullptr, E_DIM, opb, 0);
}